// round 15
// baseline (speedup 1.0000x reference)
#include <cuda_runtime.h>
#include <cuda_fp16.h>
#include <cstdint>

typedef unsigned int u32;

#define D 128
#define LDW 136     // padded smem row length (halves): 272B stride -> conflict-free LDSM
#define N_MAX 50000
#define CAP 128     // ELL slots per row (mean degree 48, max ~80; huge sigma margin)

// Scratch (static device arrays per harness rules).
// g_cursor relies on load-time zero-init + self-clearing in spmm_ell_kernel:
// every kernel_launch leaves all cursors at 0 for the next invocation.
__device__ __half g_h_half[(size_t)N_MAX * D];        // projected features, fp16 (12.8MB)
__device__ int2   g_ell[(size_t)N_MAX * CAP];         // ELL payload: (col, gate*val) (51.2MB)
__device__ int    g_cursor[N_MAX];                    // doubles as per-row count

// Side stream + events for graph-captured fork (host driver objects).
static cudaStream_t g_s2;
static cudaEvent_t  g_evFork, g_evJoin;
namespace {
struct StreamInit {
    StreamInit() {
        cudaStreamCreateWithFlags(&g_s2, cudaStreamNonBlocking);
        cudaEventCreateWithFlags(&g_evFork, cudaEventDisableTiming);
        cudaEventCreateWithFlags(&g_evJoin, cudaEventDisableTiming);
    }
};
StreamInit g_streamInit;
}

__device__ __forceinline__ u32 smem_u32(const void* p) {
    return (u32)__cvta_generic_to_shared(p);
}

__device__ __forceinline__ void ldsm_x4(u32& r0, u32& r1, u32& r2, u32& r3,
                                        u32 addr) {
    asm volatile("ldmatrix.sync.aligned.m8n8.x4.shared.b16 {%0,%1,%2,%3}, [%4];"
                 : "=r"(r0), "=r"(r1), "=r"(r2), "=r"(r3)
                 : "r"(addr));
}

__device__ __forceinline__ void mma_16816(float* c,
                                          u32 a0, u32 a1, u32 a2, u32 a3,
                                          u32 b0, u32 b1) {
    asm volatile("mma.sync.aligned.m16n8k16.row.col.f32.f16.f16.f32 "
                 "{%0,%1,%2,%3}, {%4,%5,%6,%7}, {%8,%9}, {%0,%1,%2,%3};"
                 : "+f"(c[0]), "+f"(c[1]), "+f"(c[2]), "+f"(c[3])
                 : "r"(a0), "r"(a1), "r"(a2), "r"(a3), "r"(b0), "r"(b1));
}

// ---------------------------------------------------------------------------
// Direct ELL scatter: atomic cursor bump + 8B store. Full occupancy (no smem).
// (r12-proven form)
// ---------------------------------------------------------------------------
__global__ void scatter_kernel(const int* __restrict__ rows,
                               const int* __restrict__ cols,
                               const float* __restrict__ vals,
                               const float* __restrict__ alpha,
                               int E, int GE) {
    const float ga0 = 1.f / (1.f + __expf(-__ldg(alpha + 0)));
    const float ga1 = 1.f / (1.f + __expf(-__ldg(alpha + 1)));
    const float ga2 = 1.f / (1.f + __expf(-__ldg(alpha + 2)));

    const int GE4 = GE >> 2;
    int i4 = blockIdx.x * blockDim.x + threadIdx.x;
    if (i4 < GE4) {
        int4   r = ((const int4*)rows)[i4];
        int4   c = ((const int4*)cols)[i4];
        float4 v = ((const float4*)vals)[i4];
        int e = i4 << 2;
#pragma unroll
        for (int k = 0; k < 4; k++) {
            int rr = (&r.x)[k];
            int cc = (&c.x)[k];
            float vv = (&v.x)[k];
            int ee = e + k;
            float gate = (ee < E) ? ga0 : ((ee < 2 * E) ? ga1 : ga2);
            int pos = atomicAdd(&g_cursor[rr], 1);
            if (pos < CAP)
                g_ell[(size_t)rr * CAP + pos] =
                    make_int2(cc, __float_as_int(vv * gate));
        }
    } else {
        for (int e = i4 << 2; e < GE; e++) {
            int rr = rows[e];
            float gate = (e < E) ? ga0 : ((e < 2 * E) ? ga1 : ga2);
            int pos = atomicAdd(&g_cursor[rr], 1);
            if (pos < CAP)
                g_ell[(size_t)rr * CAP + pos] =
                    make_int2(cols[e], __float_as_int(vals[e] * gate));
        }
    }
}

// ---------------------------------------------------------------------------
// GEMM: h = X @ W^T via fp16 mma.sync.m16n8k16 (fp32 accumulate).
// ---------------------------------------------------------------------------
__global__ void __launch_bounds__(256)
gemm_kernel(const float* __restrict__ X,
            const float* __restrict__ W,
            int n) {
    extern __shared__ __half sh[];
    __half* Xs = sh;                 // [128][LDW]
    __half* Ws = sh + 128 * LDW;     // [128][LDW]

    const int t = threadIdx.x;
    const int R0 = blockIdx.x * 128;

    const float4* W4 = (const float4*)W;
    for (int idx = t; idx < 128 * 32; idx += 256) {
        int r = idx >> 5, cc4 = idx & 31;
        float4 v = W4[idx];
        __half2* dst = (__half2*)(Ws + r * LDW + cc4 * 4);
        dst[0] = __floats2half2_rn(v.x, v.y);
        dst[1] = __floats2half2_rn(v.z, v.w);
    }
    const float4* X4 = (const float4*)X;
    for (int idx = t; idx < 128 * 32; idx += 256) {
        int r = idx >> 5, cc4 = idx & 31;
        int gr = R0 + r;
        float4 v = make_float4(0.f, 0.f, 0.f, 0.f);
        if (gr < n) v = X4[(size_t)gr * 32 + cc4];
        __half2* dst = (__half2*)(Xs + r * LDW + cc4 * 4);
        dst[0] = __floats2half2_rn(v.x, v.y);
        dst[1] = __floats2half2_rn(v.z, v.w);
    }
    __syncthreads();

    const int warp = t >> 5;
    const int lane = t & 31;
    const int m0 = warp * 16;

    float acc[16][4];
#pragma unroll
    for (int i = 0; i < 16; i++) {
#pragma unroll
        for (int j = 0; j < 4; j++) acc[i][j] = 0.f;
    }

    const u32 a_base =
        smem_u32(Xs + (m0 + (lane & 15)) * LDW + ((lane >> 4) << 3));
    const int b_row_off = ((lane >> 4) << 3) + (lane & 7);
    const int b_col_off = ((lane >> 3) & 1) << 3;

#pragma unroll
    for (int k0 = 0; k0 < 128; k0 += 16) {
        u32 a0, a1, a2, a3;
        ldsm_x4(a0, a1, a2, a3, a_base + (u32)(k0 * 2));
#pragma unroll
        for (int nt = 0; nt < 8; nt++) {
            u32 b0, b1, b2, b3;
            u32 baddr =
                smem_u32(Ws + (nt * 16 + b_row_off) * LDW + k0 + b_col_off);
            ldsm_x4(b0, b1, b2, b3, baddr);
            mma_16816(&acc[nt * 2][0],     a0, a1, a2, a3, b0, b1);
            mma_16816(&acc[nt * 2 + 1][0], a0, a1, a2, a3, b2, b3);
        }
    }

    const int rA = R0 + m0 + (lane >> 2);
    const int rB = rA + 8;
    const int ccol = (lane & 3) * 2;
    if (rA < n) {
#pragma unroll
        for (int nt = 0; nt < 16; nt++) {
            *(__half2*)&g_h_half[(size_t)rA * D + nt * 8 + ccol] =
                __floats2half2_rn(acc[nt][0], acc[nt][1]);
        }
    }
    if (rB < n) {
#pragma unroll
        for (int nt = 0; nt < 16; nt++) {
            *(__half2*)&g_h_half[(size_t)rB * D + nt * 8 + ccol] =
                __floats2half2_rn(acc[nt][2], acc[nt][3]);
        }
    }
}

// ---------------------------------------------------------------------------
// SPMM over ELL: warp per destination row, register accum, one 512B store.
// Full-32 passes specialized; guarded tail pass. (r12/r13-proven form)
// Self-clears the row cursor so the next invocation needs no memset.
// ---------------------------------------------------------------------------
__global__ void spmm_ell_kernel(float* __restrict__ out, int n) {
    const int warp = (blockIdx.x * blockDim.x + threadIdx.x) >> 5;
    const int lane = threadIdx.x & 31;
    if (warp >= n) return;

    const int cnt = min(g_cursor[warp], CAP);
    if (lane == 0) g_cursor[warp] = 0;   // reset for next invocation
    const int2* erow = g_ell + (size_t)warp * CAP;

    float ax = 0.f, ay = 0.f, az = 0.f, aw = 0.f;
    const __half* H = g_h_half;

    int base = 0;
    // full passes: unconditional, fully unrolled
    for (; base + 32 <= cnt; base += 32) {
        int2 cv = erow[base + lane];
#pragma unroll
        for (int jj = 0; jj < 32; jj++) {
            int   c = __shfl_sync(0xffffffffu, cv.x, jj);
            float v = __int_as_float(__shfl_sync(0xffffffffu, cv.y, jj));
            uint2 hp = *(const uint2*)(H + (size_t)c * D + lane * 4);
            float2 f01 = __half22float2(*(const __half2*)&hp.x);
            float2 f23 = __half22float2(*(const __half2*)&hp.y);
            ax = fmaf(v, f01.x, ax);
            ay = fmaf(v, f01.y, ay);
            az = fmaf(v, f23.x, az);
            aw = fmaf(v, f23.y, aw);
        }
    }
    // tail pass
    if (base < cnt) {
        int j = base + lane;
        int2 cv = make_int2(0, 0);
        if (j < cnt) cv = erow[j];
        const int m = cnt - base;
#pragma unroll 4
        for (int jj = 0; jj < m; jj++) {
            int   c = __shfl_sync(0xffffffffu, cv.x, jj);
            float v = __int_as_float(__shfl_sync(0xffffffffu, cv.y, jj));
            uint2 hp = *(const uint2*)(H + (size_t)c * D + lane * 4);
            float2 f01 = __half22float2(*(const __half2*)&hp.x);
            float2 f23 = __half22float2(*(const __half2*)&hp.y);
            ax = fmaf(v, f01.x, ax);
            ay = fmaf(v, f01.y, ay);
            az = fmaf(v, f23.x, az);
            aw = fmaf(v, f23.y, aw);
        }
    }

    ((float4*)(out + (size_t)warp * D))[lane] = make_float4(ax, ay, az, aw);
}

// ---------------------------------------------------------------------------
extern "C" void kernel_launch(void* const* d_in, const int* in_sizes, int n_in,
                              void* d_out, int out_size) {
    const float* X     = (const float*)d_in[0];
    const float* W     = (const float*)d_in[1];
    const float* alpha = (const float*)d_in[2];
    const int*   rows  = (const int*)d_in[3];
    const int*   cols  = (const int*)d_in[4];
    const float* vals  = (const float*)d_in[5];
    float* out = (float*)d_out;

    const int n  = in_sizes[0] / D;      // 50000
    const int G  = in_sizes[2];          // 3
    const int GE = in_sizes[3];          // 2400000
    const int E  = GE / G;               // 800000

    // Fork: gemm on side stream overlaps scatter on main stream.
    cudaEventRecord(g_evFork, 0);
    cudaStreamWaitEvent(g_s2, g_evFork, 0);

    // main stream: ELL scatter (cursors are zero: load-time init on first
    // call, self-cleared by spmm_ell_kernel on every call thereafter)
    scatter_kernel<<<((GE >> 2) + 255) / 256 + 1, 256>>>(rows, cols, vals,
                                                         alpha, E, GE);

    // side stream: tensor-core gemm
    const int gemmBlocks = (n + 127) / 128;        // 391
    const int smem = 2 * 128 * LDW * (int)sizeof(__half);  // 69632 B
    cudaFuncSetAttribute(gemm_kernel,
                         cudaFuncAttributeMaxDynamicSharedMemorySize, smem);
    gemm_kernel<<<gemmBlocks, 256, smem, g_s2>>>(X, W, n);

    cudaEventRecord(g_evJoin, g_s2);
    cudaStreamWaitEvent(0, g_evJoin, 0);

    // SPMM (warp per row)
    const int warps_per_block = 8;
    const int blocks = (n + warps_per_block - 1) / warps_per_block;
    spmm_ell_kernel<<<blocks, warps_per_block * 32>>>(out, n);
}

// round 16
// speedup vs baseline: 1.9814x; 1.9814x over previous
#include <cuda_runtime.h>
#include <cuda_fp16.h>
#include <cstdint>

typedef unsigned int u32;

#define D 128
#define LDW 136     // padded smem row length (halves): 272B stride -> conflict-free LDSM
#define N_MAX 50000
#define CAP 128     // ELL slots per row (mean degree 48, max ~80; huge sigma margin)

// Scratch (static device arrays per harness rules)
__device__ __half g_h_half[(size_t)N_MAX * D];        // projected features, fp16 (12.8MB)
__device__ int2   g_ell[(size_t)N_MAX * CAP];         // ELL payload: (col, gate*val) (51.2MB)
__device__ int    g_cursor[N_MAX];                    // doubles as per-row count

// Side stream + events for graph-captured fork (host driver objects).
static cudaStream_t g_s2;
static cudaEvent_t  g_evFork, g_evJoin;
namespace {
struct StreamInit {
    StreamInit() {
        cudaStreamCreateWithFlags(&g_s2, cudaStreamNonBlocking);
        cudaEventCreateWithFlags(&g_evFork, cudaEventDisableTiming);
        cudaEventCreateWithFlags(&g_evJoin, cudaEventDisableTiming);
    }
};
StreamInit g_streamInit;
}

__device__ __forceinline__ u32 smem_u32(const void* p) {
    return (u32)__cvta_generic_to_shared(p);
}

__device__ __forceinline__ void ldsm_x4(u32& r0, u32& r1, u32& r2, u32& r3,
                                        u32 addr) {
    asm volatile("ldmatrix.sync.aligned.m8n8.x4.shared.b16 {%0,%1,%2,%3}, [%4];"
                 : "=r"(r0), "=r"(r1), "=r"(r2), "=r"(r3)
                 : "r"(addr));
}

__device__ __forceinline__ void mma_16816(float* c,
                                          u32 a0, u32 a1, u32 a2, u32 a3,
                                          u32 b0, u32 b1) {
    asm volatile("mma.sync.aligned.m16n8k16.row.col.f32.f16.f16.f32 "
                 "{%0,%1,%2,%3}, {%4,%5,%6,%7}, {%8,%9}, {%0,%1,%2,%3};"
                 : "+f"(c[0]), "+f"(c[1]), "+f"(c[2]), "+f"(c[3])
                 : "r"(a0), "r"(a1), "r"(a2), "r"(a3), "r"(b0), "r"(b1));
}

// ---------------------------------------------------------------------------
// Direct ELL scatter: atomic cursor bump + 8B store. Full occupancy (no smem).
// (r12-proven form)
// ---------------------------------------------------------------------------
__global__ void scatter_kernel(const int* __restrict__ rows,
                               const int* __restrict__ cols,
                               const float* __restrict__ vals,
                               const float* __restrict__ alpha,
                               int E, int GE) {
    const float ga0 = 1.f / (1.f + __expf(-__ldg(alpha + 0)));
    const float ga1 = 1.f / (1.f + __expf(-__ldg(alpha + 1)));
    const float ga2 = 1.f / (1.f + __expf(-__ldg(alpha + 2)));

    const int GE4 = GE >> 2;
    int i4 = blockIdx.x * blockDim.x + threadIdx.x;
    if (i4 < GE4) {
        int4   r = ((const int4*)rows)[i4];
        int4   c = ((const int4*)cols)[i4];
        float4 v = ((const float4*)vals)[i4];
        int e = i4 << 2;
#pragma unroll
        for (int k = 0; k < 4; k++) {
            int rr = (&r.x)[k];
            int cc = (&c.x)[k];
            float vv = (&v.x)[k];
            int ee = e + k;
            float gate = (ee < E) ? ga0 : ((ee < 2 * E) ? ga1 : ga2);
            int pos = atomicAdd(&g_cursor[rr], 1);
            if (pos < CAP)
                g_ell[(size_t)rr * CAP + pos] =
                    make_int2(cc, __float_as_int(vv * gate));
        }
    } else {
        for (int e = i4 << 2; e < GE; e++) {
            int rr = rows[e];
            float gate = (e < E) ? ga0 : ((e < 2 * E) ? ga1 : ga2);
            int pos = atomicAdd(&g_cursor[rr], 1);
            if (pos < CAP)
                g_ell[(size_t)rr * CAP + pos] =
                    make_int2(cols[e], __float_as_int(vals[e] * gate));
        }
    }
}

// ---------------------------------------------------------------------------
// GEMM: h = X @ W^T via fp16 mma.sync.m16n8k16 (fp32 accumulate).
// ---------------------------------------------------------------------------
__global__ void __launch_bounds__(256)
gemm_kernel(const float* __restrict__ X,
            const float* __restrict__ W,
            int n) {
    extern __shared__ __half sh[];
    __half* Xs = sh;                 // [128][LDW]
    __half* Ws = sh + 128 * LDW;     // [128][LDW]

    const int t = threadIdx.x;
    const int R0 = blockIdx.x * 128;

    const float4* W4 = (const float4*)W;
    for (int idx = t; idx < 128 * 32; idx += 256) {
        int r = idx >> 5, cc4 = idx & 31;
        float4 v = W4[idx];
        __half2* dst = (__half2*)(Ws + r * LDW + cc4 * 4);
        dst[0] = __floats2half2_rn(v.x, v.y);
        dst[1] = __floats2half2_rn(v.z, v.w);
    }
    const float4* X4 = (const float4*)X;
    for (int idx = t; idx < 128 * 32; idx += 256) {
        int r = idx >> 5, cc4 = idx & 31;
        int gr = R0 + r;
        float4 v = make_float4(0.f, 0.f, 0.f, 0.f);
        if (gr < n) v = X4[(size_t)gr * 32 + cc4];
        __half2* dst = (__half2*)(Xs + r * LDW + cc4 * 4);
        dst[0] = __floats2half2_rn(v.x, v.y);
        dst[1] = __floats2half2_rn(v.z, v.w);
    }
    __syncthreads();

    const int warp = t >> 5;
    const int lane = t & 31;
    const int m0 = warp * 16;

    float acc[16][4];
#pragma unroll
    for (int i = 0; i < 16; i++) {
#pragma unroll
        for (int j = 0; j < 4; j++) acc[i][j] = 0.f;
    }

    const u32 a_base =
        smem_u32(Xs + (m0 + (lane & 15)) * LDW + ((lane >> 4) << 3));
    const int b_row_off = ((lane >> 4) << 3) + (lane & 7);
    const int b_col_off = ((lane >> 3) & 1) << 3;

#pragma unroll
    for (int k0 = 0; k0 < 128; k0 += 16) {
        u32 a0, a1, a2, a3;
        ldsm_x4(a0, a1, a2, a3, a_base + (u32)(k0 * 2));
#pragma unroll
        for (int nt = 0; nt < 8; nt++) {
            u32 b0, b1, b2, b3;
            u32 baddr =
                smem_u32(Ws + (nt * 16 + b_row_off) * LDW + k0 + b_col_off);
            ldsm_x4(b0, b1, b2, b3, baddr);
            mma_16816(&acc[nt * 2][0],     a0, a1, a2, a3, b0, b1);
            mma_16816(&acc[nt * 2 + 1][0], a0, a1, a2, a3, b2, b3);
        }
    }

    const int rA = R0 + m0 + (lane >> 2);
    const int rB = rA + 8;
    const int ccol = (lane & 3) * 2;
    if (rA < n) {
#pragma unroll
        for (int nt = 0; nt < 16; nt++) {
            *(__half2*)&g_h_half[(size_t)rA * D + nt * 8 + ccol] =
                __floats2half2_rn(acc[nt][0], acc[nt][1]);
        }
    }
    if (rB < n) {
#pragma unroll
        for (int nt = 0; nt < 16; nt++) {
            *(__half2*)&g_h_half[(size_t)rB * D + nt * 8 + ccol] =
                __floats2half2_rn(acc[nt][2], acc[nt][3]);
        }
    }
}

// ---------------------------------------------------------------------------
// SPMM over ELL: warp per destination row, register accum, one 512B store.
// Persistent grid: warp grid-stride over rows (one wave, no wave transitions).
// Inner loop is the r12/r13-proven form, untouched.
// ---------------------------------------------------------------------------
__global__ void __launch_bounds__(256)
spmm_ell_kernel(float* __restrict__ out, int n) {
    const int warp0 = (blockIdx.x * blockDim.x + threadIdx.x) >> 5;
    const int nwarps = (gridDim.x * blockDim.x) >> 5;
    const int lane = threadIdx.x & 31;
    const __half* H = g_h_half;

    for (int row = warp0; row < n; row += nwarps) {
        const int cnt = min(g_cursor[row], CAP);
        const int2* erow = g_ell + (size_t)row * CAP;

        float ax = 0.f, ay = 0.f, az = 0.f, aw = 0.f;

        int base = 0;
        // full passes: unconditional, fully unrolled
        for (; base + 32 <= cnt; base += 32) {
            int2 cv = erow[base + lane];
#pragma unroll
            for (int jj = 0; jj < 32; jj++) {
                int   c = __shfl_sync(0xffffffffu, cv.x, jj);
                float v = __int_as_float(__shfl_sync(0xffffffffu, cv.y, jj));
                uint2 hp = *(const uint2*)(H + (size_t)c * D + lane * 4);
                float2 f01 = __half22float2(*(const __half2*)&hp.x);
                float2 f23 = __half22float2(*(const __half2*)&hp.y);
                ax = fmaf(v, f01.x, ax);
                ay = fmaf(v, f01.y, ay);
                az = fmaf(v, f23.x, az);
                aw = fmaf(v, f23.y, aw);
            }
        }
        // tail pass
        if (base < cnt) {
            int j = base + lane;
            int2 cv = make_int2(0, 0);
            if (j < cnt) cv = erow[j];
            const int m = cnt - base;
#pragma unroll 4
            for (int jj = 0; jj < m; jj++) {
                int   c = __shfl_sync(0xffffffffu, cv.x, jj);
                float v = __int_as_float(__shfl_sync(0xffffffffu, cv.y, jj));
                uint2 hp = *(const uint2*)(H + (size_t)c * D + lane * 4);
                float2 f01 = __half22float2(*(const __half2*)&hp.x);
                float2 f23 = __half22float2(*(const __half2*)&hp.y);
                ax = fmaf(v, f01.x, ax);
                ay = fmaf(v, f01.y, ay);
                az = fmaf(v, f23.x, az);
                aw = fmaf(v, f23.y, aw);
            }
        }

        ((float4*)(out + (size_t)row * D))[lane] = make_float4(ax, ay, az, aw);
    }
}

// ---------------------------------------------------------------------------
extern "C" void kernel_launch(void* const* d_in, const int* in_sizes, int n_in,
                              void* d_out, int out_size) {
    const float* X     = (const float*)d_in[0];
    const float* W     = (const float*)d_in[1];
    const float* alpha = (const float*)d_in[2];
    const int*   rows  = (const int*)d_in[3];
    const int*   cols  = (const int*)d_in[4];
    const float* vals  = (const float*)d_in[5];
    float* out = (float*)d_out;

    const int n  = in_sizes[0] / D;      // 50000
    const int G  = in_sizes[2];          // 3
    const int GE = in_sizes[3];          // 2400000
    const int E  = GE / G;               // 800000

    // Fork: gemm on side stream overlaps scatter on main stream.
    cudaEventRecord(g_evFork, 0);
    cudaStreamWaitEvent(g_s2, g_evFork, 0);

    // main stream: cursor memset + ELL scatter
    void* curPtr = 0;
    cudaGetSymbolAddress(&curPtr, g_cursor);
    cudaMemsetAsync(curPtr, 0, (size_t)n * sizeof(int), 0);
    scatter_kernel<<<((GE >> 2) + 255) / 256 + 1, 256>>>(rows, cols, vals,
                                                         alpha, E, GE);

    // side stream: tensor-core gemm
    const int gemmBlocks = (n + 127) / 128;        // 391
    const int smem = 2 * 128 * LDW * (int)sizeof(__half);  // 69632 B
    cudaFuncSetAttribute(gemm_kernel,
                         cudaFuncAttributeMaxDynamicSharedMemorySize, smem);
    gemm_kernel<<<gemmBlocks, 256, smem, g_s2>>>(X, W, n);

    cudaEventRecord(g_evJoin, g_s2);
    cudaStreamWaitEvent(0, g_evJoin, 0);

    // SPMM: persistent grid, one wave (148 SMs x 8 CTAs)
    spmm_ell_kernel<<<148 * 8, 256>>>(out, n);
}

// round 17
// speedup vs baseline: 2.1429x; 1.0815x over previous
#include <cuda_runtime.h>
#include <cuda_fp16.h>
#include <cstdint>

typedef unsigned int u32;

#define D 128
#define LDW 136     // padded smem row length (halves): 272B stride -> conflict-free LDSM
#define N_MAX 50000
#define CAP 128     // ELL slots per row (mean degree 48, max ~80; huge sigma margin)

// Scratch (static device arrays per harness rules)
__device__ __half g_h_half[(size_t)N_MAX * D];        // projected features, fp16 (12.8MB)
__device__ int2   g_ell[(size_t)N_MAX * CAP];         // ELL payload: (col, gate*val) (51.2MB)
__device__ int    g_cursor[N_MAX];                    // doubles as per-row count

// Side stream + events for graph-captured fork (host driver objects).
static cudaStream_t g_s2;
static cudaEvent_t  g_evFork, g_evJoin;
namespace {
struct StreamInit {
    StreamInit() {
        cudaStreamCreateWithFlags(&g_s2, cudaStreamNonBlocking);
        cudaEventCreateWithFlags(&g_evFork, cudaEventDisableTiming);
        cudaEventCreateWithFlags(&g_evJoin, cudaEventDisableTiming);
    }
};
StreamInit g_streamInit;
}

__device__ __forceinline__ u32 smem_u32(const void* p) {
    return (u32)__cvta_generic_to_shared(p);
}

__device__ __forceinline__ void ldsm_x4(u32& r0, u32& r1, u32& r2, u32& r3,
                                        u32 addr) {
    asm volatile("ldmatrix.sync.aligned.m8n8.x4.shared.b16 {%0,%1,%2,%3}, [%4];"
                 : "=r"(r0), "=r"(r1), "=r"(r2), "=r"(r3)
                 : "r"(addr));
}

__device__ __forceinline__ void mma_16816(float* c,
                                          u32 a0, u32 a1, u32 a2, u32 a3,
                                          u32 b0, u32 b1) {
    asm volatile("mma.sync.aligned.m16n8k16.row.col.f32.f16.f16.f32 "
                 "{%0,%1,%2,%3}, {%4,%5,%6,%7}, {%8,%9}, {%0,%1,%2,%3};"
                 : "+f"(c[0]), "+f"(c[1]), "+f"(c[2]), "+f"(c[3])
                 : "r"(a0), "r"(a1), "r"(a2), "r"(a3), "r"(b0), "r"(b1));
}

// ---------------------------------------------------------------------------
// Direct ELL scatter: atomic cursor bump + 8B store. Full occupancy (no smem).
// ---------------------------------------------------------------------------
__global__ void scatter_kernel(const int* __restrict__ rows,
                               const int* __restrict__ cols,
                               const float* __restrict__ vals,
                               const float* __restrict__ alpha,
                               int E, int GE) {
    const float ga0 = 1.f / (1.f + __expf(-__ldg(alpha + 0)));
    const float ga1 = 1.f / (1.f + __expf(-__ldg(alpha + 1)));
    const float ga2 = 1.f / (1.f + __expf(-__ldg(alpha + 2)));

    const int GE4 = GE >> 2;
    int i4 = blockIdx.x * blockDim.x + threadIdx.x;
    if (i4 < GE4) {
        int4   r = ((const int4*)rows)[i4];
        int4   c = ((const int4*)cols)[i4];
        float4 v = ((const float4*)vals)[i4];
        int e = i4 << 2;
#pragma unroll
        for (int k = 0; k < 4; k++) {
            int rr = (&r.x)[k];
            int cc = (&c.x)[k];
            float vv = (&v.x)[k];
            int ee = e + k;
            float gate = (ee < E) ? ga0 : ((ee < 2 * E) ? ga1 : ga2);
            int pos = atomicAdd(&g_cursor[rr], 1);
            if (pos < CAP)
                g_ell[(size_t)rr * CAP + pos] =
                    make_int2(cc, __float_as_int(vv * gate));
        }
    } else {
        for (int e = i4 << 2; e < GE; e++) {
            int rr = rows[e];
            float gate = (e < E) ? ga0 : ((e < 2 * E) ? ga1 : ga2);
            int pos = atomicAdd(&g_cursor[rr], 1);
            if (pos < CAP)
                g_ell[(size_t)rr * CAP + pos] =
                    make_int2(cols[e], __float_as_int(vals[e] * gate));
        }
    }
}

// ---------------------------------------------------------------------------
// GEMM: h = X @ W^T via fp16 mma.sync.m16n8k16 (fp32 accumulate).
// ---------------------------------------------------------------------------
__global__ void __launch_bounds__(256)
gemm_kernel(const float* __restrict__ X,
            const float* __restrict__ W,
            int n) {
    extern __shared__ __half sh[];
    __half* Xs = sh;                 // [128][LDW]
    __half* Ws = sh + 128 * LDW;     // [128][LDW]

    const int t = threadIdx.x;
    const int R0 = blockIdx.x * 128;

    const float4* W4 = (const float4*)W;
    for (int idx = t; idx < 128 * 32; idx += 256) {
        int r = idx >> 5, cc4 = idx & 31;
        float4 v = W4[idx];
        __half2* dst = (__half2*)(Ws + r * LDW + cc4 * 4);
        dst[0] = __floats2half2_rn(v.x, v.y);
        dst[1] = __floats2half2_rn(v.z, v.w);
    }
    const float4* X4 = (const float4*)X;
    for (int idx = t; idx < 128 * 32; idx += 256) {
        int r = idx >> 5, cc4 = idx & 31;
        int gr = R0 + r;
        float4 v = make_float4(0.f, 0.f, 0.f, 0.f);
        if (gr < n) v = X4[(size_t)gr * 32 + cc4];
        __half2* dst = (__half2*)(Xs + r * LDW + cc4 * 4);
        dst[0] = __floats2half2_rn(v.x, v.y);
        dst[1] = __floats2half2_rn(v.z, v.w);
    }
    __syncthreads();

    const int warp = t >> 5;
    const int lane = t & 31;
    const int m0 = warp * 16;

    float acc[16][4];
#pragma unroll
    for (int i = 0; i < 16; i++) {
#pragma unroll
        for (int j = 0; j < 4; j++) acc[i][j] = 0.f;
    }

    const u32 a_base =
        smem_u32(Xs + (m0 + (lane & 15)) * LDW + ((lane >> 4) << 3));
    const int b_row_off = ((lane >> 4) << 3) + (lane & 7);
    const int b_col_off = ((lane >> 3) & 1) << 3;

#pragma unroll
    for (int k0 = 0; k0 < 128; k0 += 16) {
        u32 a0, a1, a2, a3;
        ldsm_x4(a0, a1, a2, a3, a_base + (u32)(k0 * 2));
#pragma unroll
        for (int nt = 0; nt < 8; nt++) {
            u32 b0, b1, b2, b3;
            u32 baddr =
                smem_u32(Ws + (nt * 16 + b_row_off) * LDW + k0 + b_col_off);
            ldsm_x4(b0, b1, b2, b3, baddr);
            mma_16816(&acc[nt * 2][0],     a0, a1, a2, a3, b0, b1);
            mma_16816(&acc[nt * 2 + 1][0], a0, a1, a2, a3, b2, b3);
        }
    }

    const int rA = R0 + m0 + (lane >> 2);
    const int rB = rA + 8;
    const int ccol = (lane & 3) * 2;
    if (rA < n) {
#pragma unroll
        for (int nt = 0; nt < 16; nt++) {
            *(__half2*)&g_h_half[(size_t)rA * D + nt * 8 + ccol] =
                __floats2half2_rn(acc[nt][0], acc[nt][1]);
        }
    }
    if (rB < n) {
#pragma unroll
        for (int nt = 0; nt < 16; nt++) {
            *(__half2*)&g_h_half[(size_t)rB * D + nt * 8 + ccol] =
                __floats2half2_rn(acc[nt][2], acc[nt][3]);
        }
    }
}

// ---------------------------------------------------------------------------
// SPMM over ELL: warp per destination row, register accum, one 512B store.
// Full-32 passes specialized; guarded tail pass. (r13-proven form)
// ---------------------------------------------------------------------------
__global__ void spmm_ell_kernel(float* __restrict__ out, int n) {
    const int warp = (blockIdx.x * blockDim.x + threadIdx.x) >> 5;
    const int lane = threadIdx.x & 31;
    if (warp >= n) return;

    const int cnt = min(g_cursor[warp], CAP);
    const int2* erow = g_ell + (size_t)warp * CAP;

    float ax = 0.f, ay = 0.f, az = 0.f, aw = 0.f;
    const __half* H = g_h_half;

    int base = 0;
    // full passes: unconditional, fully unrolled
    for (; base + 32 <= cnt; base += 32) {
        int2 cv = erow[base + lane];
#pragma unroll
        for (int jj = 0; jj < 32; jj++) {
            int   c = __shfl_sync(0xffffffffu, cv.x, jj);
            float v = __int_as_float(__shfl_sync(0xffffffffu, cv.y, jj));
            uint2 hp = *(const uint2*)(H + (size_t)c * D + lane * 4);
            float2 f01 = __half22float2(*(const __half2*)&hp.x);
            float2 f23 = __half22float2(*(const __half2*)&hp.y);
            ax = fmaf(v, f01.x, ax);
            ay = fmaf(v, f01.y, ay);
            az = fmaf(v, f23.x, az);
            aw = fmaf(v, f23.y, aw);
        }
    }
    // tail pass
    if (base < cnt) {
        int j = base + lane;
        int2 cv = make_int2(0, 0);
        if (j < cnt) cv = erow[j];
        const int m = cnt - base;
#pragma unroll 4
        for (int jj = 0; jj < m; jj++) {
            int   c = __shfl_sync(0xffffffffu, cv.x, jj);
            float v = __int_as_float(__shfl_sync(0xffffffffu, cv.y, jj));
            uint2 hp = *(const uint2*)(H + (size_t)c * D + lane * 4);
            float2 f01 = __half22float2(*(const __half2*)&hp.x);
            float2 f23 = __half22float2(*(const __half2*)&hp.y);
            ax = fmaf(v, f01.x, ax);
            ay = fmaf(v, f01.y, ay);
            az = fmaf(v, f23.x, az);
            aw = fmaf(v, f23.y, aw);
        }
    }

    ((float4*)(out + (size_t)warp * D))[lane] = make_float4(ax, ay, az, aw);
}

// ---------------------------------------------------------------------------
extern "C" void kernel_launch(void* const* d_in, const int* in_sizes, int n_in,
                              void* d_out, int out_size) {
    const float* X     = (const float*)d_in[0];
    const float* W     = (const float*)d_in[1];
    const float* alpha = (const float*)d_in[2];
    const int*   rows  = (const int*)d_in[3];
    const int*   cols  = (const int*)d_in[4];
    const float* vals  = (const float*)d_in[5];
    float* out = (float*)d_out;

    const int n  = in_sizes[0] / D;      // 50000
    const int G  = in_sizes[2];          // 3
    const int GE = in_sizes[3];          // 2400000
    const int E  = GE / G;               // 800000

    // Fork: gemm on side stream overlaps scatter on main stream.
    cudaEventRecord(g_evFork, 0);
    cudaStreamWaitEvent(g_s2, g_evFork, 0);

    // main stream: cursor memset + ELL scatter
    void* curPtr = 0;
    cudaGetSymbolAddress(&curPtr, g_cursor);
    cudaMemsetAsync(curPtr, 0, (size_t)n * sizeof(int), 0);
    scatter_kernel<<<((GE >> 2) + 255) / 256 + 1, 256>>>(rows, cols, vals,
                                                         alpha, E, GE);

    // side stream: tensor-core gemm
    const int gemmBlocks = (n + 127) / 128;        // 391
    const int smem = 2 * 128 * LDW * (int)sizeof(__half);  // 69632 B
    cudaFuncSetAttribute(gemm_kernel,
                         cudaFuncAttributeMaxDynamicSharedMemorySize, smem);
    gemm_kernel<<<gemmBlocks, 256, smem, g_s2>>>(X, W, n);

    cudaEventRecord(g_evJoin, g_s2);
    cudaStreamWaitEvent(0, g_evJoin, 0);

    // SPMM (warp per row)
    const int warps_per_block = 8;
    const int blocks = (n + warps_per_block - 1) / warps_per_block;
    spmm_ell_kernel<<<blocks, warps_per_block * 32>>>(out, n);
}